// round 2
// baseline (speedup 1.0000x reference)
#include <cuda_runtime.h>
#include <math.h>

// Problem constants
#define Bsz   128
#define Nn    512
#define GJ    1536          // 3*512 gate columns (wr/ul/wl flat rows)
#define GJ2   3072          // wr + ur combined output cols
#define MROWS (Bsz*Nn)      // 65536
#define NCOLB 48            // 3072/64 col blocks in recurrent GEMM

// ---------------- device scratch (allocation-free) ---------------------------
__device__ float g_Ubuf[(size_t)MROWS * GJ];   // emb@ul^T + bias   [gid][g*512+h]
__device__ float g_LW  [(size_t)MROWS * GJ];   // emb@wl^T          [gid][(g,p,r)]
__device__ float g_rlin[(size_t)MROWS * GJ];   // ph@ur^T per node  [gid][g*512+k]
__device__ float g_cbuf[(size_t)MROWS * 512];  // cell state
__device__ float g_pooled[(size_t)MROWS * 24]; // pooled bilinear   [gid][g*8+p]

__device__ int g_level[MROWS];
__device__ int g_lcount[512];
__device__ int g_lstart[513];
__device__ int g_lcur[512];
__device__ int g_nodelist[MROWS];
__device__ int g_maxlev;

// grid barrier state
__device__ unsigned g_gcnt = 0;
__device__ unsigned g_ggen = 0;

// ---------------- level metadata kernels ------------------------------------
__global__ void zero_counts() {
    g_lcount[threadIdx.x] = 0;
}

__global__ void build_depth(const int* __restrict__ nc) {
    __shared__ int spar[512];
    __shared__ unsigned short dep[512];
    const int b = blockIdx.x;
    for (int t = threadIdx.x; t < 512; t += 32) spar[t] = nc[b * 512 + t];
    __syncthreads();
    if (threadIdx.x == 0) {
        for (int t = 0; t < 512; t++) {
            int par = spar[t];
            dep[t] = (t > 0 && par < t) ? (unsigned short)(dep[par] + 1) : 0;
        }
    }
    __syncthreads();
    for (int t = threadIdx.x; t < 512; t += 32) {
        int lv = dep[t];
        g_level[b * 512 + t] = lv;
        atomicAdd(&g_lcount[lv], 1);
    }
}

__global__ void prefix_levels() {
    int sum = 0, mx = 0;
    for (int l = 0; l < 512; l++) {
        g_lstart[l] = sum;
        g_lcur[l]   = sum;
        if (g_lcount[l] > 0) mx = l;
        sum += g_lcount[l];
    }
    g_lstart[512] = sum;
    g_maxlev = mx;
}

__global__ void scatter_levels() {
    int i = blockIdx.x * 512 + threadIdx.x;
    if (i < MROWS) {
        int pos = atomicAdd(&g_lcur[g_level[i]], 1);
        g_nodelist[pos] = i;
    }
}

// ---------------- precompute GEMM: C[M x 1536] = A[M x 512] @ W[1536 x 512]^T (+bias)
__global__ __launch_bounds__(256) void gemm_pre(
    const float* __restrict__ A, const float* __restrict__ W,
    const float* __restrict__ bias, int sel)
{
    __shared__ __align__(16) float As[2][16][128];
    __shared__ __align__(16) float Bs[2][16][64];

    float* C = sel ? g_LW : g_Ubuf;

    const int tid = threadIdx.x;
    const int tx = tid & 15, ty = tid >> 4;
    const int r0 = blockIdx.y * 128;
    const int c0 = blockIdx.x * 64;

    const float* Ab = A + (size_t)r0 * 512;
    const float* Wb = W + (size_t)c0 * 512;

    const int am = tid >> 2;
    const int ak = (tid & 3) * 4;
    const int wn = tid >> 2;
    const int wk = (tid & 3) * 4;

    float4 pa0, pa1, pw;

    pa0 = *(const float4*)(Ab + (size_t)am * 512 + ak);
    pa1 = *(const float4*)(Ab + (size_t)(am + 64) * 512 + ak);
    pw  = *(const float4*)(Wb + (size_t)wn * 512 + wk);

    As[0][ak + 0][am] = pa0.x; As[0][ak + 1][am] = pa0.y;
    As[0][ak + 2][am] = pa0.z; As[0][ak + 3][am] = pa0.w;
    As[0][ak + 0][am + 64] = pa1.x; As[0][ak + 1][am + 64] = pa1.y;
    As[0][ak + 2][am + 64] = pa1.z; As[0][ak + 3][am + 64] = pa1.w;
    Bs[0][wk + 0][wn] = pw.x; Bs[0][wk + 1][wn] = pw.y;
    Bs[0][wk + 2][wn] = pw.z; Bs[0][wk + 3][wn] = pw.w;
    __syncthreads();

    float acc[8][4];
    #pragma unroll
    for (int i = 0; i < 8; i++)
        #pragma unroll
        for (int j = 0; j < 4; j++) acc[i][j] = 0.f;

    for (int kt = 0; kt < 32; kt++) {
        const int cur = kt & 1;
        if (kt < 31) {
            const int kk = (kt + 1) * 16;
            pa0 = *(const float4*)(Ab + (size_t)am * 512 + kk + ak);
            pa1 = *(const float4*)(Ab + (size_t)(am + 64) * 512 + kk + ak);
            pw  = *(const float4*)(Wb + (size_t)wn * 512 + kk + wk);
        }
        #pragma unroll
        for (int k = 0; k < 16; k++) {
            float4 a0 = *(const float4*)&As[cur][k][ty * 8];
            float4 a1 = *(const float4*)&As[cur][k][ty * 8 + 4];
            float4 bb = *(const float4*)&Bs[cur][k][tx * 4];
            float av[8] = {a0.x, a0.y, a0.z, a0.w, a1.x, a1.y, a1.z, a1.w};
            float bv[4] = {bb.x, bb.y, bb.z, bb.w};
            #pragma unroll
            for (int i = 0; i < 8; i++)
                #pragma unroll
                for (int j = 0; j < 4; j++) acc[i][j] += av[i] * bv[j];
        }
        if (kt < 31) {
            const int nb = cur ^ 1;
            As[nb][ak + 0][am] = pa0.x; As[nb][ak + 1][am] = pa0.y;
            As[nb][ak + 2][am] = pa0.z; As[nb][ak + 3][am] = pa0.w;
            As[nb][ak + 0][am + 64] = pa1.x; As[nb][ak + 1][am + 64] = pa1.y;
            As[nb][ak + 2][am + 64] = pa1.z; As[nb][ak + 3][am + 64] = pa1.w;
            Bs[nb][wk + 0][wn] = pw.x; Bs[nb][wk + 1][wn] = pw.y;
            Bs[nb][wk + 2][wn] = pw.z; Bs[nb][wk + 3][wn] = pw.w;
        }
        __syncthreads();
    }

    float b0 = 0.f, b1 = 0.f, b2 = 0.f, b3 = 0.f;
    if (bias) {
        float4 bb = *(const float4*)(bias + c0 + tx * 4);
        b0 = bb.x; b1 = bb.y; b2 = bb.z; b3 = bb.w;
    }
    #pragma unroll
    for (int i = 0; i < 8; i++) {
        float4 o;
        o.x = acc[i][0] + b0; o.y = acc[i][1] + b1;
        o.z = acc[i][2] + b2; o.w = acc[i][3] + b3;
        *(float4*)(C + (size_t)(r0 + ty * 8 + i) * GJ + c0 + tx * 4) = o;
    }
}

// ---------------- persistent level-scan kernel -------------------------------
__global__ __launch_bounds__(256, 2) void scan_levels(
    float* __restrict__ out,         // d_out = h buffer
    const int* __restrict__ nc,
    const float* __restrict__ wr,    // (1536, 512)
    const float* __restrict__ ur,    // (1536, 512)
    const float* __restrict__ wo)    // (3, 512, 8)
{
    __shared__ __align__(16) float As[2][16][68];
    __shared__ __align__(16) float Bs[2][16][68];
    __shared__ int rowoff[64];
    __shared__ int rowgid[64];
    __shared__ float plbuf[24];

    const int tid = threadIdx.x;
    const int tx  = tid & 15, ty = tid >> 4;
    const int lr  = tid >> 2;          // 0..63  load row
    const int lk  = (tid & 3) * 4;     // 0,4,8,12
    const unsigned ncta = gridDim.x;

    const unsigned base = *(volatile unsigned*)&g_ggen;
    unsigned nbar = 0;
    const int maxlev = g_maxlev;

    for (int lev = 0; lev <= maxlev; lev++) {
        const int s = g_lstart[lev];
        const int R = g_lstart[lev + 1] - s;
        const int nrb = (R + 63) >> 6;
        const int units = nrb * NCOLB;

        // ---------------- phase 1: recurrent GEMM + pooling ----------------
        for (int u = blockIdx.x; u < units; u += ncta) {
            const int rb = u / NCOLB;
            const int cb = u - rb * NCOLB;
            const int row0 = rb << 6;

            if (tid < 64) {
                int r = row0 + tid;
                int off = -1, gid = -1;
                if (r < R) {
                    gid = g_nodelist[s + r];
                    int b = gid >> 9, t = gid & 511;
                    int par = nc[(b << 9) + t];
                    if (t > 0 && par < t) off = ((b << 9) + par) << 9;
                }
                rowgid[tid] = gid;
                rowoff[tid] = off;
            }
            __syncthreads();

            const int aoff = rowoff[lr];
            const float* Wb = (cb < 24)
                ? (wr + ((size_t)cb << 15))
                : (ur + ((size_t)(cb - 24) << 15));

            float4 pa, pw;
            pa = (aoff >= 0) ? *(const float4*)(out + (size_t)aoff + lk)
                             : make_float4(0.f, 0.f, 0.f, 0.f);
            pw = *(const float4*)(Wb + ((size_t)lr << 9) + lk);

            As[0][lk + 0][lr] = pa.x; As[0][lk + 1][lr] = pa.y;
            As[0][lk + 2][lr] = pa.z; As[0][lk + 3][lr] = pa.w;
            Bs[0][lk + 0][lr] = pw.x; Bs[0][lk + 1][lr] = pw.y;
            Bs[0][lk + 2][lr] = pw.z; Bs[0][lk + 3][lr] = pw.w;
            __syncthreads();

            float acc[4][4];
            #pragma unroll
            for (int i = 0; i < 4; i++)
                #pragma unroll
                for (int j = 0; j < 4; j++) acc[i][j] = 0.f;

            for (int kt = 0; kt < 32; kt++) {
                const int cur = kt & 1;
                if (kt < 31) {
                    const int kk = (kt + 1) * 16;
                    pa = (aoff >= 0) ? *(const float4*)(out + (size_t)aoff + kk + lk)
                                     : make_float4(0.f, 0.f, 0.f, 0.f);
                    pw = *(const float4*)(Wb + ((size_t)lr << 9) + kk + lk);
                }
                #pragma unroll
                for (int k = 0; k < 16; k++) {
                    float4 a4 = *(const float4*)&As[cur][k][ty << 2];
                    float4 b4 = *(const float4*)&Bs[cur][k][tx << 2];
                    float av[4] = {a4.x, a4.y, a4.z, a4.w};
                    float bv[4] = {b4.x, b4.y, b4.z, b4.w};
                    #pragma unroll
                    for (int i = 0; i < 4; i++)
                        #pragma unroll
                        for (int j = 0; j < 4; j++) acc[i][j] += av[i] * bv[j];
                }
                if (kt < 31) {
                    const int nb = cur ^ 1;
                    As[nb][lk + 0][lr] = pa.x; As[nb][lk + 1][lr] = pa.y;
                    As[nb][lk + 2][lr] = pa.z; As[nb][lk + 3][lr] = pa.w;
                    Bs[nb][lk + 0][lr] = pw.x; Bs[nb][lk + 1][lr] = pw.y;
                    Bs[nb][lk + 2][lr] = pw.z; Bs[nb][lk + 3][lr] = pw.w;
                }
                __syncthreads();
            }

            if (cb < 24) {
                // bilinear pooling: multiply by LW, reduce over r (64 cols = one (g,p))
                #pragma unroll
                for (int i = 0; i < 4; i++) {
                    const int rr = (ty << 2) + i;
                    const int gid = rowgid[rr];
                    float v = 0.f;
                    if (gid >= 0) {
                        float4 lw4 = *(const float4*)(g_LW + (size_t)gid * GJ + (cb << 6) + (tx << 2));
                        v = acc[i][0] * lw4.x + acc[i][1] * lw4.y
                          + acc[i][2] * lw4.z + acc[i][3] * lw4.w;
                    }
                    v += __shfl_xor_sync(0xffffffffu, v, 1);
                    v += __shfl_xor_sync(0xffffffffu, v, 2);
                    v += __shfl_xor_sync(0xffffffffu, v, 4);
                    v += __shfl_xor_sync(0xffffffffu, v, 8);
                    if (tx == 0 && gid >= 0)
                        g_pooled[(size_t)gid * 24 + cb] = v;
                }
            } else {
                const int j0 = ((cb - 24) << 6) + (tx << 2);
                #pragma unroll
                for (int i = 0; i < 4; i++) {
                    const int rr = (ty << 2) + i;
                    const int gid = rowgid[rr];
                    if (gid >= 0) {
                        float4 o;
                        o.x = acc[i][0]; o.y = acc[i][1];
                        o.z = acc[i][2]; o.w = acc[i][3];
                        *(float4*)(g_rlin + (size_t)gid * GJ + j0) = o;
                    }
                }
            }
            __syncthreads();
        }

        // grid barrier ------------------------------------------------------
        nbar++;
        __syncthreads();
        if (tid == 0) {
            __threadfence();
            unsigned arrived = atomicAdd(&g_gcnt, 1u);
            if (arrived == ncta - 1u) {
                g_gcnt = 0;
                __threadfence();
                atomicAdd(&g_ggen, 1u);
            } else {
                while ((*(volatile unsigned*)&g_ggen) - base < nbar) { }
            }
            __threadfence();
        }
        __syncthreads();

        // ---------------- phase 2: gate assembly + activations --------------
        for (int r = blockIdx.x; r < R; r += ncta) {
            const int gid = g_nodelist[s + r];
            const int b = gid >> 9, t = gid & 511;
            if (tid < 24) plbuf[tid] = g_pooled[(size_t)gid * 24 + tid];
            __syncthreads();

            const int par = nc[(b << 9) + t];
            const bool hasp = (t > 0 && par < t);
            const size_t pbase = hasp ? ((size_t)((b << 9) + par) << 9) : 0;
            const size_t ubase = (size_t)gid * GJ;
            const size_t obase = (size_t)gid << 9;

            #pragma unroll
            for (int hh = 0; hh < 2; hh++) {
                const int h = (hh << 8) + tid;
                float gate[3];
                #pragma unroll
                for (int g = 0; g < 3; g++) {
                    float sg = g_Ubuf[ubase + (g << 9) + h] + g_rlin[ubase + (g << 9) + h];
                    const float* wop = wo + (((size_t)(g << 9) + h) << 3);
                    float4 w0 = *(const float4*)(wop);
                    float4 w1 = *(const float4*)(wop + 4);
                    sg += plbuf[(g << 3) + 0] * w0.x + plbuf[(g << 3) + 1] * w0.y
                        + plbuf[(g << 3) + 2] * w0.z + plbuf[(g << 3) + 3] * w0.w
                        + plbuf[(g << 3) + 4] * w1.x + plbuf[(g << 3) + 5] * w1.y
                        + plbuf[(g << 3) + 6] * w1.z + plbuf[(g << 3) + 7] * w1.w;
                    gate[g] = sg;
                }
                const float f = 1.f / (1.f + expf(-gate[0]));
                const float o = 1.f / (1.f + expf(-gate[1]));
                const float z = tanhf(gate[2]);
                const float pc = hasp ? g_cbuf[pbase + h] : 0.f;
                const float c = pc * f + (1.f - f) * z;
                g_cbuf[obase + h] = c;
                out[obase + h] = o * tanhf(c);
            }
            __syncthreads();
        }

        // grid barrier ------------------------------------------------------
        nbar++;
        __syncthreads();
        if (tid == 0) {
            __threadfence();
            unsigned arrived = atomicAdd(&g_gcnt, 1u);
            if (arrived == ncta - 1u) {
                g_gcnt = 0;
                __threadfence();
                atomicAdd(&g_ggen, 1u);
            } else {
                while ((*(volatile unsigned*)&g_ggen) - base < nbar) { }
            }
            __threadfence();
        }
        __syncthreads();
    }
}

// ---------------------------- launch ----------------------------------------
extern "C" void kernel_launch(void* const* d_in, const int* in_sizes, int n_in,
                              void* d_out, int out_size)
{
    (void)in_sizes; (void)n_in; (void)out_size;
    const float* emb  = (const float*)d_in[0];
    const int*   nc   = (const int*)d_in[1];
    // d_in[2] = node_mask (unused by reference)
    const float* wl   = (const float*)d_in[3];
    const float* wr   = (const float*)d_in[4];
    const float* wo   = (const float*)d_in[5];
    const float* ul   = (const float*)d_in[6];
    const float* ur   = (const float*)d_in[7];
    const float* bias = (const float*)d_in[8];
    float* out = (float*)d_out;

    // level metadata (cheap, rebuilt every replay)
    zero_counts<<<1, 512>>>();
    build_depth<<<128, 32>>>(nc);
    prefix_levels<<<1, 1>>>();
    scatter_levels<<<128, 512>>>();

    // precompute: Ubuf = emb@ul^T + bias ; LW = emb@wl^T
    dim3 gp(GJ / 64, MROWS / 128);   // (24, 512)
    gemm_pre<<<gp, 256>>>(emb, ul, bias, 0);
    gemm_pre<<<gp, 256>>>(emb, wl, nullptr, 1);

    // single persistent kernel handles the whole level-ordered scan
    scan_levels<<<296, 256>>>(out, nc, wr, ur, wo);
}

// round 3
// speedup vs baseline: 1.8609x; 1.8609x over previous
#include <cuda_runtime.h>
#include <math.h>

// Problem constants
#define Bsz   128
#define Nn    512
#define GJ    1536          // 3*512 gate columns
#define MROWS (Bsz*Nn)      // 65536
#define NCOLB 48            // 3072/64 col blocks in recurrent GEMM

// ---------------- device scratch (allocation-free) ---------------------------
__device__ float g_Ubuf[(size_t)MROWS * GJ];   // emb@ul^T + bias
__device__ float g_LW  [(size_t)MROWS * GJ];   // emb@wl^T
__device__ float g_rlin[(size_t)MROWS * GJ];   // ph@ur^T
__device__ float g_cbuf[(size_t)MROWS * 512];  // cell state
__device__ float g_pooled[(size_t)MROWS * 24]; // pooled bilinear

__device__ int g_level[MROWS];
__device__ int g_lcount[512];
__device__ int g_lstart[513];
__device__ int g_lcur[512];
__device__ int g_nodelist[MROWS];
__device__ int g_maxlev;

__device__ unsigned g_gcnt = 0;
__device__ unsigned g_ggen = 0;

// ---------------- tf32 helpers ----------------------------------------------
__device__ __forceinline__ unsigned f2t(float x) {
    unsigned u; asm("cvt.rna.tf32.f32 %0, %1;" : "=r"(u) : "f"(x)); return u;
}
__device__ __forceinline__ void st_tf32_4(float* dst, float4 v) {
    uint4 u; u.x = f2t(v.x); u.y = f2t(v.y); u.z = f2t(v.z); u.w = f2t(v.w);
    *(uint4*)dst = u;
}
__device__ __forceinline__ void mma8(float* c, const unsigned* a, const unsigned* b) {
    asm volatile(
        "mma.sync.aligned.m16n8k8.row.col.f32.tf32.tf32.f32 "
        "{%0,%1,%2,%3},{%4,%5,%6,%7},{%8,%9},{%0,%1,%2,%3};"
        : "+f"(c[0]), "+f"(c[1]), "+f"(c[2]), "+f"(c[3])
        : "r"(a[0]), "r"(a[1]), "r"(a[2]), "r"(a[3]), "r"(b[0]), "r"(b[1]));
}

// ---------------- level metadata kernels ------------------------------------
__global__ void zero_counts() { g_lcount[threadIdx.x] = 0; }

__global__ void build_depth(const int* __restrict__ nc) {
    __shared__ int spar[512];
    __shared__ unsigned short dep[512];
    const int b = blockIdx.x;
    for (int t = threadIdx.x; t < 512; t += 32) spar[t] = nc[b * 512 + t];
    __syncthreads();
    if (threadIdx.x == 0) {
        for (int t = 0; t < 512; t++) {
            int par = spar[t];
            dep[t] = (t > 0 && par < t) ? (unsigned short)(dep[par] + 1) : 0;
        }
    }
    __syncthreads();
    for (int t = threadIdx.x; t < 512; t += 32) {
        int lv = dep[t];
        g_level[b * 512 + t] = lv;
        atomicAdd(&g_lcount[lv], 1);
    }
}

__global__ void prefix_levels() {
    int sum = 0, mx = 0;
    for (int l = 0; l < 512; l++) {
        g_lstart[l] = sum;
        g_lcur[l]   = sum;
        if (g_lcount[l] > 0) mx = l;
        sum += g_lcount[l];
    }
    g_lstart[512] = sum;
    g_maxlev = mx;
}

__global__ void scatter_levels() {
    int i = blockIdx.x * 512 + threadIdx.x;
    if (i < MROWS) {
        int pos = atomicAdd(&g_lcur[g_level[i]], 1);
        g_nodelist[pos] = i;
    }
}

// ---------------- precompute GEMM (tf32 mma): C[Mx1536] = A[Mx512]@W^T (+bias)
// BM=128, BN=64, BK=32, 256 threads (8 warps: 4m x 2n), warp tile 32x32.
__global__ __launch_bounds__(256) void gemm_pre(
    const float* __restrict__ A, const float* __restrict__ W,
    const float* __restrict__ bias, int sel)
{
    __shared__ float As[2][128][36];
    __shared__ float Bs[2][64][36];

    float* C = sel ? g_LW : g_Ubuf;

    const int tid = threadIdx.x, lane = tid & 31, warp = tid >> 5;
    const int wm = (warp & 3) * 32, wn = (warp >> 2) * 32;
    const int g = lane >> 2, cc = lane & 3;
    const int r0 = blockIdx.y * 128, c0 = blockIdx.x * 64;
    const float* Ab = A + (size_t)r0 * 512;
    const float* Wb = W + (size_t)c0 * 512;

    const int arow = tid >> 1, acol = (tid & 1) * 16;
    const int brow = tid >> 2, bcol = (tid & 3) * 8;

    float4 pa[4], pb[2];
    #pragma unroll
    for (int i = 0; i < 4; i++) pa[i] = *(const float4*)(Ab + (size_t)arow * 512 + acol + i * 4);
    #pragma unroll
    for (int i = 0; i < 2; i++) pb[i] = *(const float4*)(Wb + (size_t)brow * 512 + bcol + i * 4);
    #pragma unroll
    for (int i = 0; i < 4; i++) st_tf32_4(&As[0][arow][acol + i * 4], pa[i]);
    #pragma unroll
    for (int i = 0; i < 2; i++) st_tf32_4(&Bs[0][brow][bcol + i * 4], pb[i]);
    __syncthreads();

    float acc[2][4][4];
    #pragma unroll
    for (int mt = 0; mt < 2; mt++)
        #pragma unroll
        for (int nt = 0; nt < 4; nt++)
            #pragma unroll
            for (int j = 0; j < 4; j++) acc[mt][nt][j] = 0.f;

    for (int kt = 0; kt < 16; kt++) {
        const int cur = kt & 1;
        if (kt < 15) {
            const int kk = (kt + 1) * 32;
            #pragma unroll
            for (int i = 0; i < 4; i++) pa[i] = *(const float4*)(Ab + (size_t)arow * 512 + kk + acol + i * 4);
            #pragma unroll
            for (int i = 0; i < 2; i++) pb[i] = *(const float4*)(Wb + (size_t)brow * 512 + kk + bcol + i * 4);
        }
        #pragma unroll
        for (int ks = 0; ks < 4; ks++) {
            const int k0 = ks * 8;
            unsigned af[2][4], bf[4][2];
            #pragma unroll
            for (int mt = 0; mt < 2; mt++) {
                const int rb = wm + mt * 16 + g;
                af[mt][0] = __float_as_uint(As[cur][rb][k0 + cc]);
                af[mt][1] = __float_as_uint(As[cur][rb + 8][k0 + cc]);
                af[mt][2] = __float_as_uint(As[cur][rb][k0 + cc + 4]);
                af[mt][3] = __float_as_uint(As[cur][rb + 8][k0 + cc + 4]);
            }
            #pragma unroll
            for (int nt = 0; nt < 4; nt++) {
                const int nb = wn + nt * 8 + g;
                bf[nt][0] = __float_as_uint(Bs[cur][nb][k0 + cc]);
                bf[nt][1] = __float_as_uint(Bs[cur][nb][k0 + cc + 4]);
            }
            #pragma unroll
            for (int mt = 0; mt < 2; mt++)
                #pragma unroll
                for (int nt = 0; nt < 4; nt++) mma8(acc[mt][nt], af[mt], bf[nt]);
        }
        if (kt < 15) {
            const int nb = cur ^ 1;
            #pragma unroll
            for (int i = 0; i < 4; i++) st_tf32_4(&As[nb][arow][acol + i * 4], pa[i]);
            #pragma unroll
            for (int i = 0; i < 2; i++) st_tf32_4(&Bs[nb][brow][bcol + i * 4], pb[i]);
        }
        __syncthreads();
    }

    // epilogue: stage fragments through smem (reuse As), coalesced store + bias
    float* stage = &As[0][0][0];   // 128*68 <= 2*128*36
    #pragma unroll
    for (int mt = 0; mt < 2; mt++)
        #pragma unroll
        for (int nt = 0; nt < 4; nt++) {
            const int row = wm + mt * 16 + g, col = wn + nt * 8 + cc * 2;
            *(float2*)&stage[row * 68 + col]       = make_float2(acc[mt][nt][0], acc[mt][nt][1]);
            *(float2*)&stage[(row + 8) * 68 + col] = make_float2(acc[mt][nt][2], acc[mt][nt][3]);
        }
    __syncthreads();
    const int rr = tid >> 1, half = tid & 1;
    #pragma unroll
    for (int i = 0; i < 8; i++) {
        const int col = half * 32 + i * 4;
        float4 v = *(float4*)&stage[rr * 68 + col];
        if (bias) {
            v.x += bias[c0 + col]; v.y += bias[c0 + col + 1];
            v.z += bias[c0 + col + 2]; v.w += bias[c0 + col + 3];
        }
        *(float4*)(C + (size_t)(r0 + rr) * GJ + c0 + col) = v;
    }
}

// ---------------- persistent level-scan kernel (tf32 mma recurrent GEMM) ----
// BM=64, BN=64, BK=32, 256 threads (8 warps: 2m x 4n), warp tile 32x16.
__global__ __launch_bounds__(256, 2) void scan_levels(
    float* __restrict__ out,
    const int* __restrict__ nc,
    const float* __restrict__ wr,    // (1536, 512)
    const float* __restrict__ ur,    // (1536, 512)
    const float* __restrict__ wo)    // (3, 512, 8)
{
    __shared__ float As[2][64][36];
    __shared__ float Bs[2][64][36];
    __shared__ int rowoff[64];
    __shared__ int rowgid[64];
    __shared__ float plbuf[24];

    const int tid = threadIdx.x, lane = tid & 31, warp = tid >> 5;
    const int wm = (warp & 1) * 32, wn = (warp >> 1) * 16;
    const int g = lane >> 2, cc = lane & 3;
    const int arow = tid >> 2, acol = (tid & 3) * 8;
    const unsigned ncta = gridDim.x;

    const unsigned base = *(volatile unsigned*)&g_ggen;
    unsigned nbar = 0;
    const int maxlev = g_maxlev;

    for (int lev = 0; lev <= maxlev; lev++) {
        const int s = g_lstart[lev];
        const int R = g_lstart[lev + 1] - s;
        const int nrb = (R + 63) >> 6;
        const int units = nrb * NCOLB;

        // ---------------- phase 1: recurrent GEMM + pooling ----------------
        for (int u = blockIdx.x; u < units; u += ncta) {
            const int rb = u / NCOLB;
            const int cb = u - rb * NCOLB;
            const int row0 = rb << 6;

            if (tid < 64) {
                int r = row0 + tid;
                int off = -1, gid = -1;
                if (r < R) {
                    gid = g_nodelist[s + r];
                    int b = gid >> 9, t = gid & 511;
                    int par = nc[(b << 9) + t];
                    if (t > 0 && par < t) off = ((b << 9) + par) << 9;
                }
                rowgid[tid] = gid;
                rowoff[tid] = off;
            }
            __syncthreads();

            const int aoff = rowoff[arow];
            const float* Wb = (cb < 24)
                ? (wr + ((size_t)cb << 15))
                : (ur + ((size_t)(cb - 24) << 15));

            float4 pa[2], pb[2];
            #pragma unroll
            for (int i = 0; i < 2; i++) {
                pa[i] = (aoff >= 0) ? *(const float4*)(out + (size_t)aoff + acol + i * 4)
                                    : make_float4(0.f, 0.f, 0.f, 0.f);
                pb[i] = *(const float4*)(Wb + (size_t)arow * 512 + acol + i * 4);
            }
            #pragma unroll
            for (int i = 0; i < 2; i++) {
                st_tf32_4(&As[0][arow][acol + i * 4], pa[i]);
                st_tf32_4(&Bs[0][arow][acol + i * 4], pb[i]);
            }
            __syncthreads();

            float acc[2][2][4];
            #pragma unroll
            for (int mt = 0; mt < 2; mt++)
                #pragma unroll
                for (int nt = 0; nt < 2; nt++)
                    #pragma unroll
                    for (int j = 0; j < 4; j++) acc[mt][nt][j] = 0.f;

            for (int kt = 0; kt < 16; kt++) {
                const int cur = kt & 1;
                if (kt < 15) {
                    const int kk = (kt + 1) * 32;
                    #pragma unroll
                    for (int i = 0; i < 2; i++) {
                        pa[i] = (aoff >= 0) ? *(const float4*)(out + (size_t)aoff + kk + acol + i * 4)
                                            : make_float4(0.f, 0.f, 0.f, 0.f);
                        pb[i] = *(const float4*)(Wb + (size_t)arow * 512 + kk + acol + i * 4);
                    }
                }
                #pragma unroll
                for (int ks = 0; ks < 4; ks++) {
                    const int k0 = ks * 8;
                    unsigned af[2][4], bf[2][2];
                    #pragma unroll
                    for (int mt = 0; mt < 2; mt++) {
                        const int rb2 = wm + mt * 16 + g;
                        af[mt][0] = __float_as_uint(As[cur][rb2][k0 + cc]);
                        af[mt][1] = __float_as_uint(As[cur][rb2 + 8][k0 + cc]);
                        af[mt][2] = __float_as_uint(As[cur][rb2][k0 + cc + 4]);
                        af[mt][3] = __float_as_uint(As[cur][rb2 + 8][k0 + cc + 4]);
                    }
                    #pragma unroll
                    for (int nt = 0; nt < 2; nt++) {
                        const int nb2 = wn + nt * 8 + g;
                        bf[nt][0] = __float_as_uint(Bs[cur][nb2][k0 + cc]);
                        bf[nt][1] = __float_as_uint(Bs[cur][nb2][k0 + cc + 4]);
                    }
                    #pragma unroll
                    for (int mt = 0; mt < 2; mt++)
                        #pragma unroll
                        for (int nt = 0; nt < 2; nt++) mma8(acc[mt][nt], af[mt], bf[nt]);
                }
                if (kt < 15) {
                    const int nb = cur ^ 1;
                    #pragma unroll
                    for (int i = 0; i < 2; i++) {
                        st_tf32_4(&As[nb][arow][acol + i * 4], pa[i]);
                        st_tf32_4(&Bs[nb][arow][acol + i * 4], pb[i]);
                    }
                }
                __syncthreads();
            }

            // stage C tile into smem (reuse As)
            float* stage = &As[0][0][0];   // 64*68 <= 2*64*36
            #pragma unroll
            for (int mt = 0; mt < 2; mt++)
                #pragma unroll
                for (int nt = 0; nt < 2; nt++) {
                    const int row = wm + mt * 16 + g, col = wn + nt * 8 + cc * 2;
                    *(float2*)&stage[row * 68 + col]       = make_float2(acc[mt][nt][0], acc[mt][nt][1]);
                    *(float2*)&stage[(row + 8) * 68 + col] = make_float2(acc[mt][nt][2], acc[mt][nt][3]);
                }
            __syncthreads();

            const int r = tid >> 2, q = tid & 3;
            const int gid = rowgid[r];
            if (cb < 24) {
                float v = 0.f;
                if (gid >= 0) {
                    const float* lwp = g_LW + (size_t)gid * GJ + (cb << 6) + q * 16;
                    #pragma unroll
                    for (int i = 0; i < 4; i++) {
                        float4 l4 = *(const float4*)(lwp + i * 4);
                        float4 c4 = *(float4*)&stage[r * 68 + q * 16 + i * 4];
                        v += c4.x * l4.x + c4.y * l4.y + c4.z * l4.z + c4.w * l4.w;
                    }
                }
                v += __shfl_xor_sync(0xffffffffu, v, 1);
                v += __shfl_xor_sync(0xffffffffu, v, 2);
                if (q == 0 && gid >= 0) g_pooled[(size_t)gid * 24 + cb] = v;
            } else {
                if (gid >= 0) {
                    const int j0 = ((cb - 24) << 6) + q * 16;
                    #pragma unroll
                    for (int i = 0; i < 4; i++) {
                        float4 c4 = *(float4*)&stage[r * 68 + q * 16 + i * 4];
                        *(float4*)(g_rlin + (size_t)gid * GJ + j0 + i * 4) = c4;
                    }
                }
            }
            __syncthreads();
        }

        // grid barrier ------------------------------------------------------
        nbar++;
        __syncthreads();
        if (tid == 0) {
            __threadfence();
            unsigned arrived = atomicAdd(&g_gcnt, 1u);
            if (arrived == ncta - 1u) {
                g_gcnt = 0;
                __threadfence();
                atomicAdd(&g_ggen, 1u);
            } else {
                while ((*(volatile unsigned*)&g_ggen) - base < nbar) { }
            }
            __threadfence();
        }
        __syncthreads();

        // ---------------- phase 2: gate assembly + activations --------------
        for (int r2 = blockIdx.x; r2 < R; r2 += ncta) {
            const int gid = g_nodelist[s + r2];
            const int b = gid >> 9, t = gid & 511;
            if (tid < 24) plbuf[tid] = g_pooled[(size_t)gid * 24 + tid];
            __syncthreads();

            const int par = nc[(b << 9) + t];
            const bool hasp = (t > 0 && par < t);
            const size_t pbase = hasp ? ((size_t)((b << 9) + par) << 9) : 0;
            const size_t ubase = (size_t)gid * GJ;
            const size_t obase = (size_t)gid << 9;

            #pragma unroll
            for (int hh = 0; hh < 2; hh++) {
                const int h = (hh << 8) + tid;
                float gate[3];
                #pragma unroll
                for (int gg = 0; gg < 3; gg++) {
                    float sg = g_Ubuf[ubase + (gg << 9) + h] + g_rlin[ubase + (gg << 9) + h];
                    const float* wop = wo + (((size_t)(gg << 9) + h) << 3);
                    float4 w0 = *(const float4*)(wop);
                    float4 w1 = *(const float4*)(wop + 4);
                    sg += plbuf[(gg << 3) + 0] * w0.x + plbuf[(gg << 3) + 1] * w0.y
                        + plbuf[(gg << 3) + 2] * w0.z + plbuf[(gg << 3) + 3] * w0.w
                        + plbuf[(gg << 3) + 4] * w1.x + plbuf[(gg << 3) + 5] * w1.y
                        + plbuf[(gg << 3) + 6] * w1.z + plbuf[(gg << 3) + 7] * w1.w;
                    gate[gg] = sg;
                }
                const float f = 1.f / (1.f + expf(-gate[0]));
                const float o = 1.f / (1.f + expf(-gate[1]));
                const float z = tanhf(gate[2]);
                const float pc = hasp ? g_cbuf[pbase + h] : 0.f;
                const float c = pc * f + (1.f - f) * z;
                g_cbuf[obase + h] = c;
                out[obase + h] = o * tanhf(c);
            }
            __syncthreads();
        }

        // grid barrier ------------------------------------------------------
        nbar++;
        __syncthreads();
        if (tid == 0) {
            __threadfence();
            unsigned arrived = atomicAdd(&g_gcnt, 1u);
            if (arrived == ncta - 1u) {
                g_gcnt = 0;
                __threadfence();
                atomicAdd(&g_ggen, 1u);
            } else {
                while ((*(volatile unsigned*)&g_ggen) - base < nbar) { }
            }
            __threadfence();
        }
        __syncthreads();
    }
}

// ---------------------------- launch ----------------------------------------
extern "C" void kernel_launch(void* const* d_in, const int* in_sizes, int n_in,
                              void* d_out, int out_size)
{
    (void)in_sizes; (void)n_in; (void)out_size;
    const float* emb  = (const float*)d_in[0];
    const int*   nc   = (const int*)d_in[1];
    // d_in[2] = node_mask (unused by reference)
    const float* wl   = (const float*)d_in[3];
    const float* wr   = (const float*)d_in[4];
    const float* wo   = (const float*)d_in[5];
    const float* ul   = (const float*)d_in[6];
    const float* ur   = (const float*)d_in[7];
    const float* bias = (const float*)d_in[8];
    float* out = (float*)d_out;

    zero_counts<<<1, 512>>>();
    build_depth<<<128, 32>>>(nc);
    prefix_levels<<<1, 1>>>();
    scatter_levels<<<128, 512>>>();

    dim3 gp(GJ / 64, MROWS / 128);   // (24, 512)
    gemm_pre<<<gp, 256>>>(emb, ul, bias, 0);
    gemm_pre<<<gp, 256>>>(emb, wl, nullptr, 1);

    scan_levels<<<296, 256>>>(out, nc, wr, ur, wo);
}

// round 4
// speedup vs baseline: 1.8716x; 1.0058x over previous
#include <cuda_runtime.h>
#include <math.h>

// Problem constants
#define Bsz   128
#define Nn    512
#define GJ    1536          // 3*512 gate columns
#define MROWS (Bsz*Nn)      // 65536
#define NCOLB 24            // 3072/128 col blocks in recurrent GEMM

// ---------------- device scratch (allocation-free) ---------------------------
__device__ float g_Ubuf[(size_t)MROWS * GJ];   // emb@ul^T + bias
__device__ float g_LW  [(size_t)MROWS * GJ];   // emb@wl^T
__device__ float g_rlin[(size_t)MROWS * GJ];   // ph@ur^T
__device__ float g_cbuf[(size_t)MROWS * 512];  // cell state
__device__ float g_pooled[(size_t)MROWS * 24]; // pooled bilinear

__device__ int g_level[MROWS];
__device__ int g_lcount[512];
__device__ int g_lstart[513];
__device__ int g_lcur[512];
__device__ int g_nodelist[MROWS];
__device__ int g_maxlev;

__device__ unsigned g_gcnt = 0;
__device__ unsigned g_ggen = 0;

// ---------------- tf32 helpers ----------------------------------------------
__device__ __forceinline__ unsigned f2t(float x) {
    unsigned u; asm("cvt.rna.tf32.f32 %0, %1;" : "=r"(u) : "f"(x)); return u;
}
__device__ __forceinline__ void st_tf32_4(float* dst, float4 v) {
    uint4 u; u.x = f2t(v.x); u.y = f2t(v.y); u.z = f2t(v.z); u.w = f2t(v.w);
    *(uint4*)dst = u;
}
__device__ __forceinline__ void mma8(float* c, const unsigned* a, const unsigned* b) {
    asm volatile(
        "mma.sync.aligned.m16n8k8.row.col.f32.tf32.tf32.f32 "
        "{%0,%1,%2,%3},{%4,%5,%6,%7},{%8,%9},{%0,%1,%2,%3};"
        : "+f"(c[0]), "+f"(c[1]), "+f"(c[2]), "+f"(c[3])
        : "r"(a[0]), "r"(a[1]), "r"(a[2]), "r"(a[3]), "r"(b[0]), "r"(b[1]));
}

// ---------------- level metadata kernels ------------------------------------
__global__ void zero_counts() { g_lcount[threadIdx.x] = 0; }

__global__ void build_depth(const int* __restrict__ nc) {
    __shared__ int spar[512];
    __shared__ unsigned short dep[512];
    const int b = blockIdx.x;
    for (int t = threadIdx.x; t < 512; t += 32) spar[t] = nc[b * 512 + t];
    __syncthreads();
    if (threadIdx.x == 0) {
        for (int t = 0; t < 512; t++) {
            int par = spar[t];
            dep[t] = (t > 0 && par < t) ? (unsigned short)(dep[par] + 1) : 0;
        }
    }
    __syncthreads();
    for (int t = threadIdx.x; t < 512; t += 32) {
        int lv = dep[t];
        g_level[b * 512 + t] = lv;
        atomicAdd(&g_lcount[lv], 1);
    }
}

__global__ void prefix_levels() {
    int sum = 0, mx = 0;
    for (int l = 0; l < 512; l++) {
        g_lstart[l] = sum;
        g_lcur[l]   = sum;
        if (g_lcount[l] > 0) mx = l;
        sum += g_lcount[l];
    }
    g_lstart[512] = sum;
    g_maxlev = mx;
}

__global__ void scatter_levels() {
    int i = blockIdx.x * 512 + threadIdx.x;
    if (i < MROWS) {
        int pos = atomicAdd(&g_lcur[g_level[i]], 1);
        g_nodelist[pos] = i;
    }
}

// ---------------- precompute GEMM (tf32 mma): C[Mx1536] = A[Mx512]@W^T (+bias)
// BM=128, BN=64, BK=32, 256 threads (8 warps: 4m x 2n), warp tile 32x32.
__global__ __launch_bounds__(256) void gemm_pre(
    const float* __restrict__ A, const float* __restrict__ W,
    const float* __restrict__ bias, int sel)
{
    __shared__ float As[2][128][36];
    __shared__ float Bs[2][64][36];

    float* C = sel ? g_LW : g_Ubuf;

    const int tid = threadIdx.x, lane = tid & 31, warp = tid >> 5;
    const int wm = (warp & 3) * 32, wn = (warp >> 2) * 32;
    const int g = lane >> 2, cc = lane & 3;
    const int r0 = blockIdx.y * 128, c0 = blockIdx.x * 64;
    const float* Ab = A + (size_t)r0 * 512;
    const float* Wb = W + (size_t)c0 * 512;

    const int arow = tid >> 1, acol = (tid & 1) * 16;
    const int brow = tid >> 2, bcol = (tid & 3) * 8;

    float4 pa[4], pb[2];
    #pragma unroll
    for (int i = 0; i < 4; i++) pa[i] = *(const float4*)(Ab + (size_t)arow * 512 + acol + i * 4);
    #pragma unroll
    for (int i = 0; i < 2; i++) pb[i] = *(const float4*)(Wb + (size_t)brow * 512 + bcol + i * 4);
    #pragma unroll
    for (int i = 0; i < 4; i++) st_tf32_4(&As[0][arow][acol + i * 4], pa[i]);
    #pragma unroll
    for (int i = 0; i < 2; i++) st_tf32_4(&Bs[0][brow][bcol + i * 4], pb[i]);
    __syncthreads();

    float acc[2][4][4];
    #pragma unroll
    for (int mt = 0; mt < 2; mt++)
        #pragma unroll
        for (int nt = 0; nt < 4; nt++)
            #pragma unroll
            for (int j = 0; j < 4; j++) acc[mt][nt][j] = 0.f;

    for (int kt = 0; kt < 16; kt++) {
        const int cur = kt & 1;
        if (kt < 15) {
            const int kk = (kt + 1) * 32;
            #pragma unroll
            for (int i = 0; i < 4; i++) pa[i] = *(const float4*)(Ab + (size_t)arow * 512 + kk + acol + i * 4);
            #pragma unroll
            for (int i = 0; i < 2; i++) pb[i] = *(const float4*)(Wb + (size_t)brow * 512 + kk + bcol + i * 4);
        }
        #pragma unroll
        for (int ks = 0; ks < 4; ks++) {
            const int k0 = ks * 8;
            unsigned af[2][4], bf[4][2];
            #pragma unroll
            for (int mt = 0; mt < 2; mt++) {
                const int rb = wm + mt * 16 + g;
                af[mt][0] = __float_as_uint(As[cur][rb][k0 + cc]);
                af[mt][1] = __float_as_uint(As[cur][rb + 8][k0 + cc]);
                af[mt][2] = __float_as_uint(As[cur][rb][k0 + cc + 4]);
                af[mt][3] = __float_as_uint(As[cur][rb + 8][k0 + cc + 4]);
            }
            #pragma unroll
            for (int nt = 0; nt < 4; nt++) {
                const int nb = wn + nt * 8 + g;
                bf[nt][0] = __float_as_uint(Bs[cur][nb][k0 + cc]);
                bf[nt][1] = __float_as_uint(Bs[cur][nb][k0 + cc + 4]);
            }
            #pragma unroll
            for (int mt = 0; mt < 2; mt++)
                #pragma unroll
                for (int nt = 0; nt < 4; nt++) mma8(acc[mt][nt], af[mt], bf[nt]);
        }
        if (kt < 15) {
            const int nb = cur ^ 1;
            #pragma unroll
            for (int i = 0; i < 4; i++) st_tf32_4(&As[nb][arow][acol + i * 4], pa[i]);
            #pragma unroll
            for (int i = 0; i < 2; i++) st_tf32_4(&Bs[nb][brow][bcol + i * 4], pb[i]);
        }
        __syncthreads();
    }

    // epilogue: stage fragments through smem (reuse As), coalesced store + bias
    float* stage = &As[0][0][0];   // 128*68 <= 2*128*36
    #pragma unroll
    for (int mt = 0; mt < 2; mt++)
        #pragma unroll
        for (int nt = 0; nt < 4; nt++) {
            const int row = wm + mt * 16 + g, col = wn + nt * 8 + cc * 2;
            *(float2*)&stage[row * 68 + col]       = make_float2(acc[mt][nt][0], acc[mt][nt][1]);
            *(float2*)&stage[(row + 8) * 68 + col] = make_float2(acc[mt][nt][2], acc[mt][nt][3]);
        }
    __syncthreads();
    const int rr = tid >> 1, half = tid & 1;
    #pragma unroll
    for (int i = 0; i < 8; i++) {
        const int col = half * 32 + i * 4;
        float4 v = *(float4*)&stage[rr * 68 + col];
        if (bias) {
            v.x += bias[c0 + col]; v.y += bias[c0 + col + 1];
            v.z += bias[c0 + col + 2]; v.w += bias[c0 + col + 3];
        }
        *(float4*)(C + (size_t)(r0 + rr) * GJ + c0 + col) = v;
    }
}

// ---------------- persistent level-scan kernel (tf32 mma recurrent GEMM) ----
// BM=64, BN=128, BK=32, 256 threads (8 warps: 2m x 4n), warp tile 32x32.
__global__ __launch_bounds__(256, 2) void scan_levels(
    float* __restrict__ out,
    const int* __restrict__ nc,
    const float* __restrict__ wr,    // (1536, 512)
    const float* __restrict__ ur,    // (1536, 512)
    const float* __restrict__ wo)    // (3, 512, 8)
{
    __shared__ float As[2][64][36];
    __shared__ float Bs[2][128][36];
    __shared__ int rowoff[64];
    __shared__ int rowgid[64];
    __shared__ float plbuf[24];

    const int tid = threadIdx.x, lane = tid & 31, warp = tid >> 5;
    const int wm = (warp & 1) * 32, wn = (warp >> 1) * 32;
    const int g = lane >> 2, cc = lane & 3;
    const int arow = tid >> 2, acol = (tid & 3) * 8;  // A loader: 2 float4
    const int brow = tid >> 1, bcol = (tid & 1) * 16; // B loader: 4 float4
    const unsigned ncta = gridDim.x;

    const unsigned base = *(volatile unsigned*)&g_ggen;
    unsigned nbar = 0;
    const int maxlev = g_maxlev;

    for (int lev = 0; lev <= maxlev; lev++) {
        const int s = g_lstart[lev];
        const int R = g_lstart[lev + 1] - s;
        const int nrb = (R + 63) >> 6;
        const int units = nrb * NCOLB;

        // ---------------- phase 1: recurrent GEMM + pooling ----------------
        for (int u = blockIdx.x; u < units; u += ncta) {
            const int rb = u / NCOLB;
            const int cb = u - rb * NCOLB;
            const int row0 = rb << 6;

            if (tid < 64) {
                int r = row0 + tid;
                int off = -1, gid = -1;
                if (r < R) {
                    gid = g_nodelist[s + r];
                    int b = gid >> 9, t = gid & 511;
                    int par = nc[(b << 9) + t];
                    if (t > 0 && par < t) off = ((b << 9) + par) << 9;
                }
                rowgid[tid] = gid;
                rowoff[tid] = off;
            }
            __syncthreads();

            const int aoff = rowoff[arow];
            const float* Wb = (cb < 12)
                ? (wr + ((size_t)cb << 16))
                : (ur + ((size_t)(cb - 12) << 16));

            float4 pa[2], pb[4];
            #pragma unroll
            for (int i = 0; i < 2; i++)
                pa[i] = (aoff >= 0) ? *(const float4*)(out + (size_t)aoff + acol + i * 4)
                                    : make_float4(0.f, 0.f, 0.f, 0.f);
            #pragma unroll
            for (int i = 0; i < 4; i++)
                pb[i] = *(const float4*)(Wb + (size_t)brow * 512 + bcol + i * 4);
            #pragma unroll
            for (int i = 0; i < 2; i++) st_tf32_4(&As[0][arow][acol + i * 4], pa[i]);
            #pragma unroll
            for (int i = 0; i < 4; i++) st_tf32_4(&Bs[0][brow][bcol + i * 4], pb[i]);
            __syncthreads();

            float acc[2][4][4];
            #pragma unroll
            for (int mt = 0; mt < 2; mt++)
                #pragma unroll
                for (int nt = 0; nt < 4; nt++)
                    #pragma unroll
                    for (int j = 0; j < 4; j++) acc[mt][nt][j] = 0.f;

            for (int kt = 0; kt < 16; kt++) {
                const int cur = kt & 1;
                if (kt < 15) {
                    const int kk = (kt + 1) * 32;
                    #pragma unroll
                    for (int i = 0; i < 2; i++)
                        pa[i] = (aoff >= 0) ? *(const float4*)(out + (size_t)aoff + kk + acol + i * 4)
                                            : make_float4(0.f, 0.f, 0.f, 0.f);
                    #pragma unroll
                    for (int i = 0; i < 4; i++)
                        pb[i] = *(const float4*)(Wb + (size_t)brow * 512 + kk + bcol + i * 4);
                }
                #pragma unroll
                for (int ks = 0; ks < 4; ks++) {
                    const int k0 = ks * 8;
                    unsigned af[2][4], bf[4][2];
                    #pragma unroll
                    for (int mt = 0; mt < 2; mt++) {
                        const int rb2 = wm + mt * 16 + g;
                        af[mt][0] = __float_as_uint(As[cur][rb2][k0 + cc]);
                        af[mt][1] = __float_as_uint(As[cur][rb2 + 8][k0 + cc]);
                        af[mt][2] = __float_as_uint(As[cur][rb2][k0 + cc + 4]);
                        af[mt][3] = __float_as_uint(As[cur][rb2 + 8][k0 + cc + 4]);
                    }
                    #pragma unroll
                    for (int nt = 0; nt < 4; nt++) {
                        const int nb2 = wn + nt * 8 + g;
                        bf[nt][0] = __float_as_uint(Bs[cur][nb2][k0 + cc]);
                        bf[nt][1] = __float_as_uint(Bs[cur][nb2][k0 + cc + 4]);
                    }
                    #pragma unroll
                    for (int mt = 0; mt < 2; mt++)
                        #pragma unroll
                        for (int nt = 0; nt < 4; nt++) mma8(acc[mt][nt], af[mt], bf[nt]);
                }
                if (kt < 15) {
                    const int nb = cur ^ 1;
                    #pragma unroll
                    for (int i = 0; i < 2; i++) st_tf32_4(&As[nb][arow][acol + i * 4], pa[i]);
                    #pragma unroll
                    for (int i = 0; i < 4; i++) st_tf32_4(&Bs[nb][brow][bcol + i * 4], pb[i]);
                }
                __syncthreads();
            }

            // epilogue: two 64-col passes staged through smem (reuse As region)
            float* stage = &As[0][0][0];   // 64*68 <= 2*64*36
            const int r = tid >> 2, q = tid & 3;
            const int gid = rowgid[r];
            #pragma unroll
            for (int p = 0; p < 2; p++) {
                if ((warp >= 4) == (p == 1)) {
                    const int colbase = wn - p * 64;  // 0 or 32
                    #pragma unroll
                    for (int mt = 0; mt < 2; mt++)
                        #pragma unroll
                        for (int nt = 0; nt < 4; nt++) {
                            const int row = wm + mt * 16 + g, col = colbase + nt * 8 + cc * 2;
                            *(float2*)&stage[row * 68 + col]       = make_float2(acc[mt][nt][0], acc[mt][nt][1]);
                            *(float2*)&stage[(row + 8) * 68 + col] = make_float2(acc[mt][nt][2], acc[mt][nt][3]);
                        }
                }
                __syncthreads();

                if (cb < 12) {
                    // bilinear pooling: 64 cols = one (g,p) group -> pooled[cb*2+p]
                    float v = 0.f;
                    if (gid >= 0) {
                        const float* lwp = g_LW + (size_t)gid * GJ + ((cb * 2 + p) << 6) + q * 16;
                        #pragma unroll
                        for (int i = 0; i < 4; i++) {
                            float4 l4 = *(const float4*)(lwp + i * 4);
                            float4 c4 = *(float4*)&stage[r * 68 + q * 16 + i * 4];
                            v += c4.x * l4.x + c4.y * l4.y + c4.z * l4.z + c4.w * l4.w;
                        }
                    }
                    v += __shfl_xor_sync(0xffffffffu, v, 1);
                    v += __shfl_xor_sync(0xffffffffu, v, 2);
                    if (q == 0 && gid >= 0) g_pooled[(size_t)gid * 24 + cb * 2 + p] = v;
                } else {
                    if (gid >= 0) {
                        const int j0 = ((cb - 12) << 7) + p * 64 + q * 16;
                        #pragma unroll
                        for (int i = 0; i < 4; i++) {
                            float4 c4 = *(float4*)&stage[r * 68 + q * 16 + i * 4];
                            *(float4*)(g_rlin + (size_t)gid * GJ + j0 + i * 4) = c4;
                        }
                    }
                }
                __syncthreads();
            }
        }

        // grid barrier ------------------------------------------------------
        nbar++;
        __syncthreads();
        if (tid == 0) {
            __threadfence();
            unsigned arrived = atomicAdd(&g_gcnt, 1u);
            if (arrived == ncta - 1u) {
                g_gcnt = 0;
                __threadfence();
                atomicAdd(&g_ggen, 1u);
            } else {
                while ((*(volatile unsigned*)&g_ggen) - base < nbar) { }
            }
            __threadfence();
        }
        __syncthreads();

        // ---------------- phase 2: gate assembly + activations --------------
        for (int r2 = blockIdx.x; r2 < R; r2 += ncta) {
            const int gid = g_nodelist[s + r2];
            const int b = gid >> 9, t = gid & 511;
            if (tid < 24) plbuf[tid] = g_pooled[(size_t)gid * 24 + tid];
            __syncthreads();

            const int par = nc[(b << 9) + t];
            const bool hasp = (t > 0 && par < t);
            const size_t pbase = hasp ? ((size_t)((b << 9) + par) << 9) : 0;
            const size_t ubase = (size_t)gid * GJ;
            const size_t obase = (size_t)gid << 9;

            #pragma unroll
            for (int hh = 0; hh < 2; hh++) {
                const int h = (hh << 8) + tid;
                float gate[3];
                #pragma unroll
                for (int gg = 0; gg < 3; gg++) {
                    float sg = g_Ubuf[ubase + (gg << 9) + h] + g_rlin[ubase + (gg << 9) + h];
                    const float* wop = wo + (((size_t)(gg << 9) + h) << 3);
                    float4 w0 = *(const float4*)(wop);
                    float4 w1 = *(const float4*)(wop + 4);
                    sg += plbuf[(gg << 3) + 0] * w0.x + plbuf[(gg << 3) + 1] * w0.y
                        + plbuf[(gg << 3) + 2] * w0.z + plbuf[(gg << 3) + 3] * w0.w
                        + plbuf[(gg << 3) + 4] * w1.x + plbuf[(gg << 3) + 5] * w1.y
                        + plbuf[(gg << 3) + 6] * w1.z + plbuf[(gg << 3) + 7] * w1.w;
                    gate[gg] = sg;
                }
                const float f = 1.f / (1.f + expf(-gate[0]));
                const float o = 1.f / (1.f + expf(-gate[1]));
                const float z = tanhf(gate[2]);
                const float pc = hasp ? g_cbuf[pbase + h] : 0.f;
                const float c = pc * f + (1.f - f) * z;
                g_cbuf[obase + h] = c;
                out[obase + h] = o * tanhf(c);
            }
            __syncthreads();
        }

        // grid barrier ------------------------------------------------------
        nbar++;
        __syncthreads();
        if (tid == 0) {
            __threadfence();
            unsigned arrived = atomicAdd(&g_gcnt, 1u);
            if (arrived == ncta - 1u) {
                g_gcnt = 0;
                __threadfence();
                atomicAdd(&g_ggen, 1u);
            } else {
                while ((*(volatile unsigned*)&g_ggen) - base < nbar) { }
            }
            __threadfence();
        }
        __syncthreads();
    }
}

// ---------------------------- launch ----------------------------------------
extern "C" void kernel_launch(void* const* d_in, const int* in_sizes, int n_in,
                              void* d_out, int out_size)
{
    (void)in_sizes; (void)n_in; (void)out_size;
    const float* emb  = (const float*)d_in[0];
    const int*   nc   = (const int*)d_in[1];
    // d_in[2] = node_mask (unused by reference)
    const float* wl   = (const float*)d_in[3];
    const float* wr   = (const float*)d_in[4];
    const float* wo   = (const float*)d_in[5];
    const float* ul   = (const float*)d_in[6];
    const float* ur   = (const float*)d_in[7];
    const float* bias = (const float*)d_in[8];
    float* out = (float*)d_out;

    zero_counts<<<1, 512>>>();
    build_depth<<<128, 32>>>(nc);
    prefix_levels<<<1, 1>>>();
    scatter_levels<<<128, 512>>>();

    dim3 gp(GJ / 64, MROWS / 128);   // (24, 512)
    gemm_pre<<<gp, 256>>>(emb, ul, bias, 0);
    gemm_pre<<<gp, 256>>>(emb, wl, nullptr, 1);

    scan_levels<<<296, 256>>>(out, nc, wr, ur, wo);
}